// round 2
// baseline (speedup 1.0000x reference)
#include <cuda_runtime.h>

// filtfilt(butter(4,0.2)) over 512 rows x 48000 fp32, per-row max-abs
// normalization, odd-reflection padding (padlen 15).
//
// Chunked-recurrence decomposition (pole radius ~0.8854 -> state decays below
// fp32 eps in ~250 samples): each pass split into independent 512-sample
// chunks with 256-sample warm-up. All global traffic staged through shared
// memory with coalesced cooperative loads/stores (R1 post-mortem: per-thread
// sequential scans were fully uncoalesced and latency-bound).

namespace {
constexpr int kRows  = 512;
constexpr int kT     = 48000;
constexpr int kPad   = 15;
constexpr int kP     = kT + 2 * kPad;            // 48030
constexpr int kChunk = 512;
constexpr int kWarm  = 256;
constexpr int kNch   = (kP + kChunk - 1) / kChunk;  // 94
constexpr int kStreams = kRows * kNch;           // 48128
constexpr int kThreads = 128;
constexpr int kBlocks  = kStreams / kThreads;    // 376 (exact)
constexpr int kTile    = 32;
constexpr int kLen     = kWarm + kChunk;         // 768
constexpr int kNtiles  = kLen / kTile;           // 24
constexpr int kStoreT  = kWarm / kTile;          // 8

constexpr float B0 = 0.004824343357716228f;
constexpr float B1 = 0.019297373430864913f;
constexpr float B2 = 0.02894606014629737f;
constexpr float A1 = -2.369513007182038f;
constexpr float A2 = 2.3139884144006455f;
constexpr float A3 = -1.0546654058785672f;
constexpr float A4 = 0.18737949236818502f;
}  // namespace

__device__ float g_y1[(size_t)kRows * kP];
__device__ float g_scale[kRows];
__device__ float g_inv[kRows];

// ---------------------------------------------------------------------------
// Kernel 1: per-row max(|x|)
// ---------------------------------------------------------------------------
__global__ void k_maxabs(const float* __restrict__ x) {
    int row = blockIdx.x;
    const float4* xr = reinterpret_cast<const float4*>(x + (size_t)row * kT);
    float m = 0.f;
    for (int i = threadIdx.x; i < kT / 4; i += 512) {
        float4 v = __ldg(xr + i);
        m = fmaxf(m, fmaxf(fmaxf(fabsf(v.x), fabsf(v.y)),
                           fmaxf(fabsf(v.z), fabsf(v.w))));
    }
    #pragma unroll
    for (int o = 16; o; o >>= 1) m = fmaxf(m, __shfl_xor_sync(0xffffffffu, m, o));
    __shared__ float sm[16];
    if ((threadIdx.x & 31) == 0) sm[threadIdx.x >> 5] = m;
    __syncthreads();
    if (threadIdx.x < 16) {
        m = sm[threadIdx.x];
        #pragma unroll
        for (int o = 8; o; o >>= 1) m = fmaxf(m, __shfl_xor_sync(0xffffu, m, o));
        if (threadIdx.x == 0) {
            g_scale[row] = m;
            g_inv[row]   = 1.0f / m;
        }
    }
}

// ---------------------------------------------------------------------------
// Padded-signal access (forward pass), n in padded coords.
//   n < 0            : 0 (lfilter zero history / pre-start)
//   0   <= n < 15    : 2*x[0]   - x[14 - n]
//   15  <= n < 15+T  : x[n-15]
//   15+T<= n         : 2*x[T-1] - x[2T + 12 - n]   (valid reads up to n<2T+12)
// ---------------------------------------------------------------------------
__device__ __forceinline__ float xp_load(const float* __restrict__ xr, int n) {
    if (n < 0) return 0.f;
    if (n < kPad) return 2.f * xr[0] - xr[14 - n];
    int m = n - kPad;
    if (m < kT) return xr[m];
    return 2.f * xr[kT - 1] - xr[2 * kT + 12 - n];
}

// ---------------------------------------------------------------------------
// Forward pass: y1[n] = sum b'_k xp[n-k] - sum a_k y1[n-k],  b' = b/scale.
// 128 streams per block, 24 tiles of 32, smem-staged coalesced I/O.
// ---------------------------------------------------------------------------
__global__ __launch_bounds__(kThreads) void k_fwd(const float* __restrict__ x) {
    __shared__ float sm[kThreads][kTile + 1];
    __shared__ int s_row[kThreads];
    __shared__ int s_n0[kThreads];

    const int tid  = threadIdx.x;
    const int lane = tid & 31;
    const int wrp  = tid >> 5;          // 0..3
    const int g    = blockIdx.x * kThreads + tid;
    const int row  = g / kNch;
    const int ch   = g - row * kNch;
    const int n0   = ch * kChunk - kWarm;
    s_row[tid] = row;
    s_n0[tid]  = n0;

    const float inv = g_inv[row];
    const float b0 = B0 * inv, b1 = B1 * inv, b2 = B2 * inv;
    const float* __restrict__ xr = x + (size_t)row * kT;

    float h0 = xp_load(xr, n0 - 1), h1 = xp_load(xr, n0 - 2);
    float h2 = xp_load(xr, n0 - 3), h3 = xp_load(xr, n0 - 4);
    float y1 = 0.f, y2 = 0.f, y3 = 0.f, y4 = 0.f;
    __syncthreads();

    for (int t = 0; t < kNtiles; ++t) {
        // Coalesced load: each warp-iteration loads 32 consecutive samples of
        // one stream. stream = 4*i + wrp, offset j = lane.
        #pragma unroll 4
        for (int i = 0; i < 32; ++i) {
            int st = (i << 2) + wrp;
            int n  = s_n0[st] + t * kTile + lane;
            const float* xs = x + (size_t)s_row[st] * kT;
            sm[st][lane] = xp_load(xs, n);
        }
        __syncthreads();

        #pragma unroll 8
        for (int j = 0; j < kTile; ++j) {
            float xn = sm[tid][j];
            float f = fmaf(b0, xn, fmaf(b1, h0, fmaf(b2, h1, fmaf(b1, h2, b0 * h3))));
            float y = fmaf(-A4, y4, f);
            y = fmaf(-A3, y3, y);
            y = fmaf(-A2, y2, y);
            y = fmaf(-A1, y1, y);
            h3 = h2; h2 = h1; h1 = h0; h0 = xn;
            y4 = y3; y3 = y2; y2 = y1; y1 = y;
            sm[tid][j] = y;
        }
        __syncthreads();

        if (t >= kStoreT) {
            #pragma unroll 4
            for (int i = 0; i < 32; ++i) {
                int st = (i << 2) + wrp;
                int n  = s_n0[st] + t * kTile + lane;
                if (n < kP) g_y1[(size_t)s_row[st] * kP + n] = sm[st][lane];
            }
        }
        // store->next-load hazard is intra-thread (same element mapping);
        // next load is ordered after this store in program order.
    }
}

// ---------------------------------------------------------------------------
// Backward pass in reversed coords m = kP-1-n: v[m] = y1[kP-1-m] (0 outside),
// y2[m] = sum B_k v[m-k] - sum a_k y2[m-k]. Store out[48014-m] * scale for
// m in [15, 48014].
// ---------------------------------------------------------------------------
__global__ __launch_bounds__(kThreads) void k_bwd(float* __restrict__ out) {
    __shared__ float sm[kThreads][kTile + 1];
    __shared__ int s_row[kThreads];
    __shared__ int s_n0[kThreads];
    __shared__ float s_scale[kThreads];

    const int tid  = threadIdx.x;
    const int lane = tid & 31;
    const int wrp  = tid >> 5;
    const int g    = blockIdx.x * kThreads + tid;
    const int row  = g / kNch;
    const int ch   = g - row * kNch;
    const int n0   = ch * kChunk - kWarm;
    s_row[tid]   = row;
    s_n0[tid]    = n0;
    s_scale[tid] = g_scale[row];

    const float* __restrict__ yr = g_y1 + (size_t)row * kP;
    auto vload = [&](const float* __restrict__ yb, int m) -> float {
        return (m >= 0 && m < kP) ? yb[kP - 1 - m] : 0.f;
    };

    float h0 = vload(yr, n0 - 1), h1 = vload(yr, n0 - 2);
    float h2 = vload(yr, n0 - 3), h3 = vload(yr, n0 - 4);
    float y1 = 0.f, y2 = 0.f, y3 = 0.f, y4 = 0.f;
    __syncthreads();

    for (int t = 0; t < kNtiles; ++t) {
        #pragma unroll 4
        for (int i = 0; i < 32; ++i) {
            int st = (i << 2) + wrp;
            int m  = s_n0[st] + t * kTile + lane;
            const float* yb = g_y1 + (size_t)s_row[st] * kP;
            sm[st][lane] = (m >= 0 && m < kP) ? yb[kP - 1 - m] : 0.f;
        }
        __syncthreads();

        #pragma unroll 8
        for (int j = 0; j < kTile; ++j) {
            float vn = sm[tid][j];
            float f = fmaf(B0, vn, fmaf(B1, h0, fmaf(B2, h1, fmaf(B1, h2, B0 * h3))));
            float y = fmaf(-A4, y4, f);
            y = fmaf(-A3, y3, y);
            y = fmaf(-A2, y2, y);
            y = fmaf(-A1, y1, y);
            h3 = h2; h2 = h1; h1 = h0; h0 = vn;
            y4 = y3; y3 = y2; y2 = y1; y1 = y;
            sm[tid][j] = y;
        }
        __syncthreads();

        if (t >= kStoreT) {
            #pragma unroll 4
            for (int i = 0; i < 32; ++i) {
                int st = (i << 2) + wrp;
                int m  = s_n0[st] + t * kTile + lane;
                if (m >= kPad && m <= kP - 1 - kPad) {
                    out[(size_t)s_row[st] * kT + (kP - 1 - kPad - m)] =
                        sm[st][lane] * s_scale[st];
                }
            }
        }
    }
}

// ---------------------------------------------------------------------------
extern "C" void kernel_launch(void* const* d_in, const int* in_sizes, int n_in,
                              void* d_out, int out_size) {
    const float* x = (const float*)d_in[0];
    float* out = (float*)d_out;

    k_maxabs<<<kRows, 512>>>(x);
    k_fwd<<<kBlocks, kThreads>>>(x);
    k_bwd<<<kBlocks, kThreads>>>(out);
}

// round 4
// speedup vs baseline: 4.8117x; 4.8117x over previous
#include <cuda_runtime.h>
#include <cstdint>

// filtfilt(butter(4,0.2)) over 512 rows x 48000 fp32, per-row max-abs
// normalization, odd-reflection padding (padlen 15).
//
// Chunked-recurrence decomposition (dominant pole radius ~0.8854, state decays
// below 3e-9 in 160 samples): each pass = independent 672-sample chunks with
// 160-sample warm-up. cp.async double-buffered smem pipeline overlaps the
// coalesced tile loads with the serial recurrence (R2 post-mortem: synchronous
// staged loads were latency-serialized).

namespace {
constexpr int kRows  = 512;
constexpr int kT     = 48000;
constexpr int kPad   = 15;
constexpr int kP     = kT + 2 * kPad;          // 48030
constexpr int kChunk = 672;
constexpr int kWarm  = 160;
constexpr int kLen   = kChunk + kWarm;         // 832
constexpr int kNch   = (kP + kChunk - 1) / kChunk;   // 72
constexpr int kStreams = kRows * kNch;         // 36864
constexpr int kThreads = 128;
constexpr int kBlocks  = kStreams / kThreads;  // 288 (exact)
constexpr int kTile    = 32;
constexpr int kNtiles  = kLen / kTile;         // 26
constexpr int kStoreT  = kWarm / kTile;        // 5
constexpr int kStride  = kTile + 1;            // 33 floats: conflict-free

constexpr float B0 = 0.004824343357716228f;
constexpr float B1 = 0.019297373430864913f;
constexpr float B2 = 0.02894606014629737f;
constexpr float A1 = -2.369513007182038f;
constexpr float A2 = 2.3139884144006455f;
constexpr float A3 = -1.0546654058785672f;
constexpr float A4 = 0.18737949236818502f;

constexpr uint32_t kXMax = (uint32_t)kRows * kT * 4u - 4u;  // clamp bound (bytes)
constexpr uint32_t kYMax = (uint32_t)kRows * kP * 4u - 4u;
}  // namespace

__device__ float g_y1[(size_t)kRows * kP];
__device__ float g_scale[kRows];
__device__ float g_inv[kRows];

// ---------------------------------------------------------------------------
__device__ __forceinline__ void cpa4(uint32_t dst, const void* src) {
    asm volatile("cp.async.ca.shared.global [%0], [%1], 4;" :: "r"(dst), "l"(src));
}
__device__ __forceinline__ void cpa_commit() {
    asm volatile("cp.async.commit_group;");
}
__device__ __forceinline__ void cpa_wait1() {
    asm volatile("cp.async.wait_group 1;");
}

// ---------------------------------------------------------------------------
// Kernel 1: per-row max(|x|)
// ---------------------------------------------------------------------------
__global__ void k_maxabs(const float* __restrict__ x) {
    int row = blockIdx.x;
    const float4* xr = reinterpret_cast<const float4*>(x + (size_t)row * kT);
    float m = 0.f;
    for (int i = threadIdx.x; i < kT / 4; i += 512) {
        float4 v = __ldg(xr + i);
        m = fmaxf(m, fmaxf(fmaxf(fabsf(v.x), fabsf(v.y)),
                           fmaxf(fabsf(v.z), fabsf(v.w))));
    }
    #pragma unroll
    for (int o = 16; o; o >>= 1) m = fmaxf(m, __shfl_xor_sync(0xffffffffu, m, o));
    __shared__ float sm[16];
    if ((threadIdx.x & 31) == 0) sm[threadIdx.x >> 5] = m;
    __syncthreads();
    if (threadIdx.x < 16) {
        m = sm[threadIdx.x];
        #pragma unroll
        for (int o = 8; o; o >>= 1) m = fmaxf(m, __shfl_xor_sync(0xffffu, m, o));
        if (threadIdx.x == 0) {
            g_scale[row] = m;
            g_inv[row]   = 1.0f / m;
        }
    }
}

// ---------------------------------------------------------------------------
// Forward pass: y1[n] = sum b'_k xp[n-k] - sum a_k y1[n-k],  b' = b/scale.
// xp: odd-reflection padded x (pad 15), zero for n<0.
// ---------------------------------------------------------------------------
__global__ __launch_bounds__(kThreads) void k_fwd(const float* __restrict__ x) {
    __shared__ float sbuf[2][kThreads][kStride];
    __shared__ int s_off[kThreads];   // byte offset of x element for n = n0
    __shared__ int s_n0[kThreads];
    __shared__ int s_sto[kThreads];   // g_y1 element index for n = n0

    const int tid = threadIdx.x, lane = tid & 31, wrp = tid >> 5;
    const int g   = blockIdx.x * kThreads + tid;
    const int row = g / kNch;
    const int ch  = g - row * kNch;
    const int n0  = ch * kChunk - kWarm;
    s_off[tid] = (row * kT + n0 - kPad) * 4;
    s_n0[tid]  = n0;
    s_sto[tid] = row * kP + n0;

    const bool is_lo = (ch == 0), is_hi = (ch == kNch - 1);
    const float inv = g_inv[row];
    const float b0 = B0 * inv, b1 = B1 * inv, b2 = B2 * inv;
    const float* __restrict__ xr = x + (size_t)row * kT;
    const float x0 = is_lo ? __ldg(xr) : 0.f;
    const float xT = is_hi ? __ldg(xr + kT - 1) : 0.f;
    const uint32_t sb = (uint32_t)__cvta_generic_to_shared(&sbuf[0][0][0]);
    __syncthreads();   // s_* tables ready

    auto load_tile = [&](int t, int b) {
        const int rel4 = (t * kTile + lane) * 4;
        const uint32_t dbase = sb + (uint32_t)(b * kThreads * kStride + lane) * 4u;
        #pragma unroll
        for (int i = 0; i < kTile; ++i) {
            const int st = (wrp << 5) + i;
            uint32_t o = min((uint32_t)(s_off[st] + rel4), kXMax);
            cpa4(dbase + (uint32_t)(st * kStride) * 4u, (const char*)x + o);
        }
        cpa_commit();
    };

    float h0 = 0.f, h1 = 0.f, h2 = 0.f, h3 = 0.f;
    float y1 = 0.f, y2 = 0.f, y3 = 0.f, y4 = 0.f;

    load_tile(0, 0);
    int buf = 0;
    #pragma unroll 1
    for (int t = 0; t < kNtiles; ++t, buf ^= 1) {
        if (t + 1 < kNtiles) load_tile(t + 1, buf ^ 1);
        else cpa_commit();
        cpa_wait1();
        __syncthreads();

        float* __restrict__ rs = &sbuf[buf][tid][0];
        const int nb = n0 + t * kTile;
        if (is_lo && nb < kPad) {
            #pragma unroll
            for (int j = 0; j < kTile; ++j) {
                int n = nb + j;
                if (n < 0) rs[j] = 0.f;
                else if (n < kPad) rs[j] = 2.f * x0 - __ldg(xr + (14 - n));
            }
        }
        if (is_hi && nb + kTile > kPad + kT) {
            #pragma unroll
            for (int j = 0; j < kTile; ++j) {
                int n = nb + j;
                if (n >= kPad + kT && n < kP)
                    rs[j] = 2.f * xT - __ldg(xr + (2 * kT + 12 - n));
            }
        }
        #pragma unroll
        for (int j = 0; j < kTile; ++j) {
            float xn = rs[j];
            float f = fmaf(b0, xn, fmaf(b1, h0, fmaf(b2, h1, fmaf(b1, h2, b0 * h3))));
            float y = fmaf(-A4, y4, f);
            y = fmaf(-A3, y3, y);
            y = fmaf(-A2, y2, y);
            y = fmaf(-A1, y1, y);
            h3 = h2; h2 = h1; h1 = h0; h0 = xn;
            y4 = y3; y3 = y2; y2 = y1; y1 = y;
            rs[j] = y;
        }
        __syncthreads();

        if (t >= kStoreT) {
            const int rel = t * kTile + lane;
            #pragma unroll
            for (int i = 0; i < kTile; ++i) {
                const int st = (wrp << 5) + i;
                if (s_n0[st] + rel < kP) g_y1[s_sto[st] + rel] = sbuf[buf][st][lane];
            }
        }
    }
}

// ---------------------------------------------------------------------------
// Backward pass in reversed coords m = kP-1-n: v[m] = y1[kP-1-m] (0 for m<0),
// y2[m] = sum (B_k*scale) v[m-k] - sum a_k y2[m-k].
// Store out[row, 48014 - m] for m in [15, 48014].
// ---------------------------------------------------------------------------
__global__ __launch_bounds__(kThreads) void k_bwd(float* __restrict__ out) {
    __shared__ float sbuf[2][kThreads][kStride];
    __shared__ int s_off[kThreads];   // byte offset of y1 element for m = n0
    __shared__ int s_n0[kThreads];
    __shared__ int s_sto[kThreads];   // out element index for m = n0

    const int tid = threadIdx.x, lane = tid & 31, wrp = tid >> 5;
    const int g   = blockIdx.x * kThreads + tid;
    const int row = g / kNch;
    const int ch  = g - row * kNch;
    const int n0  = ch * kChunk - kWarm;
    s_off[tid] = (row * kP + (kP - 1 - n0)) * 4;
    s_n0[tid]  = n0;
    s_sto[tid] = row * kT + (kP - 1 - kPad) - n0;

    const bool is_lo = (ch == 0);
    const float sc = g_scale[row];
    const float b0 = B0 * sc, b1 = B1 * sc, b2 = B2 * sc;
    const float* ybase = &g_y1[0];
    const uint32_t sb = (uint32_t)__cvta_generic_to_shared(&sbuf[0][0][0]);
    __syncthreads();

    auto load_tile = [&](int t, int b) {
        const int rel4 = (t * kTile + lane) * 4;
        const uint32_t dbase = sb + (uint32_t)(b * kThreads * kStride + lane) * 4u;
        #pragma unroll
        for (int i = 0; i < kTile; ++i) {
            const int st = (wrp << 5) + i;
            uint32_t o = min((uint32_t)(s_off[st] - rel4), kYMax);
            cpa4(dbase + (uint32_t)(st * kStride) * 4u, (const char*)ybase + o);
        }
        cpa_commit();
    };

    float h0 = 0.f, h1 = 0.f, h2 = 0.f, h3 = 0.f;
    float y1 = 0.f, y2 = 0.f, y3 = 0.f, y4 = 0.f;

    load_tile(0, 0);
    int buf = 0;
    #pragma unroll 1
    for (int t = 0; t < kNtiles; ++t, buf ^= 1) {
        if (t + 1 < kNtiles) load_tile(t + 1, buf ^ 1);
        else cpa_commit();
        cpa_wait1();
        __syncthreads();

        float* __restrict__ rs = &sbuf[buf][tid][0];
        const int nb = n0 + t * kTile;
        if (is_lo && nb < 0) {
            #pragma unroll
            for (int j = 0; j < kTile; ++j) {
                if (nb + j < 0) rs[j] = 0.f;
            }
        }
        #pragma unroll
        for (int j = 0; j < kTile; ++j) {
            float vn = rs[j];
            float f = fmaf(b0, vn, fmaf(b1, h0, fmaf(b2, h1, fmaf(b1, h2, b0 * h3))));
            float y = fmaf(-A4, y4, f);
            y = fmaf(-A3, y3, y);
            y = fmaf(-A2, y2, y);
            y = fmaf(-A1, y1, y);
            h3 = h2; h2 = h1; h1 = h0; h0 = vn;
            y4 = y3; y3 = y2; y2 = y1; y1 = y;
            rs[j] = y;
        }
        __syncthreads();

        if (t >= kStoreT) {
            const int rel = t * kTile + lane;
            #pragma unroll
            for (int i = 0; i < kTile; ++i) {
                const int st = (wrp << 5) + i;
                const int m = s_n0[st] + rel;
                if (m >= kPad && m <= kP - 1 - kPad)
                    out[s_sto[st] - rel] = sbuf[buf][st][lane];
            }
        }
    }
}

// ---------------------------------------------------------------------------
extern "C" void kernel_launch(void* const* d_in, const int* in_sizes, int n_in,
                              void* d_out, int out_size) {
    const float* x = (const float*)d_in[0];
    float* out = (float*)d_out;

    k_maxabs<<<kRows, 512>>>(x);
    k_fwd<<<kBlocks, kThreads>>>(x);
    k_bwd<<<kBlocks, kThreads>>>(out);
}